// round 1
// baseline (speedup 1.0000x reference)
#include <cuda_runtime.h>

#define BSZ    512
#define NN     128
#define NMAT   2560
#define STRIDE 132          // 128 + 4: 16B-aligned, conflict-free padding

// ---------------- persistent scratch (__device__ globals: no allocation) ----
__device__ float g_Ts[128];          // sorted thresholds
__device__ int   g_perm[128];        // sort permutation
__device__ float g_A [129 * 128];    // slope table  per interval
__device__ float g_Cc[129 * 128];    // offset table per interval (incl b2)
__device__ int   g_kidx[BSZ * NN];   // interval index per input scalar

// ---------------- kernel 1: rank thresholds (counting sort, 1 block) --------
__global__ void k_rank(const float* __restrict__ w1, const float* __restrict__ b1)
{
    __shared__ float tsh[128];
    int l = threadIdx.x;
    float w  = w1[l];
    float bb = b1[l];
    float tv;
    if (w != 0.0f) tv = -bb / w;
    else           tv = (bb > 0.0f) ? -3.0e38f : 3.0e38f;  // always/never active
    tsh[l] = tv;
    __syncthreads();
    int r = 0;
    for (int p = 0; p < 128; ++p) {
        float o = tsh[p];
        r += (o < tv) || (o == tv && p < l);   // strict total order -> permutation
    }
    g_Ts[r]   = tv;
    g_perm[r] = l;
}

// ---------------- kernel 2: interval tables A,C  [129 x 128] ----------------
// For x in interval k: active units = {w1>0, rank<k} U {w1<0 (or w1==0,b1<=0 "never"), rank>=k}
__global__ void k_tables(const float* __restrict__ w1, const float* __restrict__ b1,
                         const float* __restrict__ w2, const float* __restrict__ b2)
{
    int k = blockIdx.x;       // 0..128
    int j = threadIdx.x;      // 0..127
    float a = 0.f, c = 0.f;
    for (int p = 0; p < 128; ++p) {
        int   l  = g_perm[p];
        float w  = w1[l];
        float bb = b1[l];
        bool pos = (w > 0.f) || (w == 0.f && bb > 0.f);
        bool act = pos ? (p < k) : (p >= k);
        if (act) {
            float wv = w2[j * 128 + l];
            a = fmaf(w,  wv, a);
            c = fmaf(bb, wv, c);
        }
    }
    g_A [k * 128 + j] = a;
    g_Cc[k * 128 + j] = c + b2[j];
}

// ---------------- kernel 3: interval index per scalar -----------------------
__global__ void k_kidx(const float* __restrict__ x)
{
    int i = blockIdx.x * blockDim.x + threadIdx.x;
    if (i >= BSZ * NN) return;
    float xv = x[i];
    int lo = 0, hi = 128;
    while (lo < hi) {                       // count of thresholds < xv
        int mid = (lo + hi) >> 1;
        if (g_Ts[mid] < xv) lo = mid + 1; else hi = mid;
    }
    g_kidx[i] = lo;
}

// ---------------- kernel 4: main Sinkhorn, one CTA per matrix ---------------
__global__ __launch_bounds__(128, 2) void k_sinkhorn(
    const float* __restrict__ x,
    const float* __restrict__ noise,
    float* __restrict__ out)
{
    extern __shared__ float sm[];
    float* M  = sm;                        // [128][STRIDE]
    float* Rv = sm + 128 * STRIDE;         // [128]
    float* Cv = Rv + 128;                  // [128]
    float* xs = Cv + 128;                  // [128]
    int*   ks = (int*)(xs + 128);          // [128]

    const int m   = blockIdx.x;
    const int b   = m & (BSZ - 1);
    const int tid = threadIdx.x;
    const int c4  = tid & 31;              // column-quad within a row pass
    const int rh  = tid >> 5;              // warp id = row offset within pass

    xs[tid] = x[b * NN + tid];
    ks[tid] = g_kidx[b * NN + tid];
    Cv[tid] = 1.0f;
    __syncthreads();

    // ---- prologue: M0[r][j] = exp(A[k_r][j]*x_r + C[k_r][j] + noise[m][r][j])
    const float* nz = noise + (size_t)m * (NN * NN);
    #pragma unroll 4
    for (int p = 0; p < 32; ++p) {
        int   r  = 4 * p + rh;
        int   kr = ks[r];
        float xv = xs[r];
        float4 a4 = *(const float4*)(g_A  + kr * 128 + 4 * c4);
        float4 q4 = *(const float4*)(g_Cc + kr * 128 + 4 * c4);
        float4 n4 = *(const float4*)(nz + r * 128 + 4 * c4);
        float4 e;
        e.x = __expf(fmaf(a4.x, xv, q4.x) + n4.x);
        e.y = __expf(fmaf(a4.y, xv, q4.y) + n4.y);
        e.z = __expf(fmaf(a4.z, xv, q4.z) + n4.z);
        e.w = __expf(fmaf(a4.w, xv, q4.w) + n4.w);
        *(float4*)(M + r * STRIDE + 4 * c4) = e;   // 4-phase optimal (stride 132)
    }
    __syncthreads();

    // ---- own row -> registers (read-only for all 10 iterations)
    float4 rr[32];
    #pragma unroll
    for (int q = 0; q < 32; ++q)
        rr[q] = *(const float4*)(M + tid * STRIDE + 4 * q);

    // ---- Sinkhorn: R = 1/(M0 C);  C = 1/(M0^T R)   x10
    float Ri = 0.f;
    for (int it = 0; it < 10; ++it) {
        // row GEMV: local dot(row, C)
        float4 acc = make_float4(0.f, 0.f, 0.f, 0.f);
        #pragma unroll
        for (int q = 0; q < 32; ++q) {
            float4 cq = *(const float4*)(Cv + 4 * q);   // broadcast LDS
            acc.x = fmaf(rr[q].x, cq.x, acc.x);
            acc.y = fmaf(rr[q].y, cq.y, acc.y);
            acc.z = fmaf(rr[q].z, cq.z, acc.z);
            acc.w = fmaf(rr[q].w, cq.w, acc.w);
        }
        float s = (acc.x + acc.y) + (acc.z + acc.w);
        Ri = __fdividef(1.0f, s);
        Rv[tid] = Ri;
        __syncthreads();

        // col GEMV: t_j = sum_i M0[i][j] * R[i]   (conflict-free strided LDS)
        float t0 = 0.f, t1 = 0.f, t2 = 0.f, t3 = 0.f;
        #pragma unroll
        for (int q = 0; q < 32; ++q) {
            float4 rq = *(const float4*)(Rv + 4 * q);   // broadcast LDS
            t0 = fmaf(M[(4 * q + 0) * STRIDE + tid], rq.x, t0);
            t1 = fmaf(M[(4 * q + 1) * STRIDE + tid], rq.y, t1);
            t2 = fmaf(M[(4 * q + 2) * STRIDE + tid], rq.z, t2);
            t3 = fmaf(M[(4 * q + 3) * STRIDE + tid], rq.w, t3);
        }
        float t = (t0 + t1) + (t2 + t3);
        Cv[tid] = __fdividef(1.0f, t);
        __syncthreads();
    }

    // ---- epilogue: out[m][a][b'] = M0[b'][a] * R_b' * C_a  (transpose via smem)
    // overwrite M: M[a][i] = M0[i][a] * R_i  (thread i writes column i, conflict-free)
    #pragma unroll
    for (int q = 0; q < 32; ++q) {
        M[(4 * q + 0) * STRIDE + tid] = rr[q].x * Ri;
        M[(4 * q + 1) * STRIDE + tid] = rr[q].y * Ri;
        M[(4 * q + 2) * STRIDE + tid] = rr[q].z * Ri;
        M[(4 * q + 3) * STRIDE + tid] = rr[q].w * Ri;
    }
    __syncthreads();

    float* outm = out + (size_t)m * (NN * NN);
    #pragma unroll 4
    for (int p = 0; p < 32; ++p) {
        int   a  = 4 * p + rh;
        float ca = Cv[a];                                // broadcast
        float4 v = *(const float4*)(M + a * STRIDE + 4 * c4);
        v.x *= ca; v.y *= ca; v.z *= ca; v.w *= ca;
        *(float4*)(outm + a * 128 + 4 * c4) = v;         // coalesced STG.128
    }
}

// ---------------- launch ----------------------------------------------------
extern "C" void kernel_launch(void* const* d_in, const int* in_sizes, int n_in,
                              void* d_out, int out_size)
{
    const float* x     = (const float*)d_in[0];
    const float* w1    = (const float*)d_in[1];
    const float* b1    = (const float*)d_in[2];
    const float* w2    = (const float*)d_in[3];
    const float* b2    = (const float*)d_in[4];
    const float* noise = (const float*)d_in[5];
    float* out = (float*)d_out;

    k_rank  <<<1,   128>>>(w1, b1);
    k_tables<<<129, 128>>>(w1, b1, w2, b2);
    k_kidx  <<<256, 256>>>(x);

    const int smem_bytes = (128 * STRIDE + 4 * 128) * 4;   // 69632
    cudaFuncSetAttribute(k_sinkhorn, cudaFuncAttributeMaxDynamicSharedMemorySize,
                         smem_bytes);
    k_sinkhorn<<<NMAT, 128, smem_bytes>>>(x, noise, out);
}